// round 17
// baseline (speedup 1.0000x reference)
#include <cuda_runtime.h>
#include <cuda_bf16.h>
#include <cmath>
#include <cstdint>

#define B_  4
#define T_  2048
#define D_  1024
#define H_  16
#define DH_ 64

// ---------------------------------------------------------------------------
// Scratch — identical static set to the passing R11-R13 kernels.
// ---------------------------------------------------------------------------
__device__ __align__(16) float g_q[B_ * H_ * T_ * DH_];      // [B,H,T,dh] fp32
__device__ __align__(16) float g_k[B_ * H_ * T_ * DH_];
__device__ __align__(16) float g_v[B_ * H_ * T_ * DH_];
__device__ __align__(16) float g_attn[B_ * T_ * D_];         // [B,T,D] fp32

// ---------------------------------------------------------------------------
// PTX helpers: ldmatrix / mma.sync only
// ---------------------------------------------------------------------------
struct U4  { uint32_t x, y, z, w; };
struct F4a { float    x, y, z, w; };

__device__ __forceinline__ uint32_t smem_u32(const void* p) {
    uint32_t a;
    asm("{ .reg .u64 t; cvta.to.shared.u64 t, %1; cvt.u32.u64 %0, t; }" : "=r"(a) : "l"(p));
    return a;
}
__device__ __forceinline__ void ldsm4(U4& r, uint32_t addr) {
    asm volatile("ldmatrix.sync.aligned.m8n8.x4.shared.b16 {%0,%1,%2,%3}, [%4];"
                 : "=r"(r.x), "=r"(r.y), "=r"(r.z), "=r"(r.w) : "r"(addr));
}
__device__ __forceinline__ void ldsm4t(U4& r, uint32_t addr) {
    asm volatile("ldmatrix.sync.aligned.m8n8.x4.trans.shared.b16 {%0,%1,%2,%3}, [%4];"
                 : "=r"(r.x), "=r"(r.y), "=r"(r.z), "=r"(r.w) : "r"(addr));
}
__device__ __forceinline__ void mma(F4a& d, const U4& a, uint32_t b0, uint32_t b1) {
    asm volatile(
        "mma.sync.aligned.m16n8k16.row.col.f32.bf16.bf16.f32 "
        "{%0,%1,%2,%3}, {%4,%5,%6,%7}, {%8,%9}, {%0,%1,%2,%3};"
        : "+f"(d.x), "+f"(d.y), "+f"(d.z), "+f"(d.w)
        : "r"(a.x), "r"(a.y), "r"(a.z), "r"(a.w), "r"(b0), "r"(b1));
}

// Convert 8 fp32 (two float4) -> 16B hi chunk + 16B lo chunk (bf16x2 packed)
__device__ __forceinline__ void cvt8(const float4 f0, const float4 f1,
                                     uint4& hi, uint4& lo)
{
    __nv_bfloat16 h0 = __float2bfloat16_rn(f0.x);
    __nv_bfloat16 h1 = __float2bfloat16_rn(f0.y);
    __nv_bfloat16 h2 = __float2bfloat16_rn(f0.z);
    __nv_bfloat16 h3 = __float2bfloat16_rn(f0.w);
    __nv_bfloat16 h4 = __float2bfloat16_rn(f1.x);
    __nv_bfloat16 h5 = __float2bfloat16_rn(f1.y);
    __nv_bfloat16 h6 = __float2bfloat16_rn(f1.z);
    __nv_bfloat16 h7 = __float2bfloat16_rn(f1.w);
    __nv_bfloat16 l0 = __float2bfloat16_rn(f0.x - __bfloat162float(h0));
    __nv_bfloat16 l1 = __float2bfloat16_rn(f0.y - __bfloat162float(h1));
    __nv_bfloat16 l2 = __float2bfloat16_rn(f0.z - __bfloat162float(h2));
    __nv_bfloat16 l3 = __float2bfloat16_rn(f0.w - __bfloat162float(h3));
    __nv_bfloat16 l4 = __float2bfloat16_rn(f1.x - __bfloat162float(h4));
    __nv_bfloat16 l5 = __float2bfloat16_rn(f1.y - __bfloat162float(h5));
    __nv_bfloat16 l6 = __float2bfloat16_rn(f1.z - __bfloat162float(h6));
    __nv_bfloat16 l7 = __float2bfloat16_rn(f1.w - __bfloat162float(h7));
    __nv_bfloat162 p;
    p = __nv_bfloat162(h0, h1); hi.x = *(uint32_t*)&p;
    p = __nv_bfloat162(h2, h3); hi.y = *(uint32_t*)&p;
    p = __nv_bfloat162(h4, h5); hi.z = *(uint32_t*)&p;
    p = __nv_bfloat162(h6, h7); hi.w = *(uint32_t*)&p;
    p = __nv_bfloat162(l0, l1); lo.x = *(uint32_t*)&p;
    p = __nv_bfloat162(l2, l3); lo.y = *(uint32_t*)&p;
    p = __nv_bfloat162(l4, l5); lo.z = *(uint32_t*)&p;
    p = __nv_bfloat162(l6, l7); lo.w = *(uint32_t*)&p;
}

#define MMA3(Dst, b0h, b1h, b0l, b1l)  \
    mma(Dst, aH, b0h, b1h);            \
    mma(Dst, aH, b0l, b1l);            \
    mma(Dst, aL, b0h, b1h);

// ---------------------------------------------------------------------------
// Fused convert+mma GEMM, BIG tile: CTA 128(M) x 128(N), BK=64, 64KB smem,
//   8 warps (2m x 4n), warp tile 64x32, acc = 64 regs/thread (calibrated ~110).
// ---------------------------------------------------------------------------
#define GK   1024
#define BK   64
#define NKB  (GK / BK)   // 16
#define G_AH 0
#define G_AL 16384
#define G_BH 32768
#define G_BL 49152
#define GEMM_SMEM 65536

#define EPI(C, MT, NT) do {                                                        \
    const int r_lo = row0 + wm * 64 + (MT) * 16 + (lane >> 2);                     \
    const int r_hi = r_lo + 8;                                                     \
    const int col  = col0 + wn * 32 + (NT) * 8 + 2 * (lane & 3);                   \
    const float b0 = bias[col], b1 = bias[col + 1];                                \
    float2 vlo = make_float2((C).x + b0, (C).y + b1);                              \
    float2 vhi = make_float2((C).z + b0, (C).w + b1);                              \
    if (MODE == 0) {                                                               \
        *(float2*)(out + (size_t)r_lo * 1024 + col) = vlo;                         \
        *(float2*)(out + (size_t)r_hi * 1024 + col) = vhi;                         \
    } else {                                                                       \
        const int sec  = col >> 10;                                               \
        const int cc   = col & 1023;                                              \
        const int head = cc >> 6;                                                 \
        const int dd   = cc & 63;                                                 \
        float* buf = (sec == 0) ? g_q : (sec == 1) ? g_k : g_v;                    \
        { const int bb = r_lo >> 11, t = r_lo & 2047;                              \
          *(float2*)(buf + ((size_t)(bb * H_ + head) * T_ + t) * DH_ + dd) = vlo; }\
        { const int bb = r_hi >> 11, t = r_hi & 2047;                              \
          *(float2*)(buf + ((size_t)(bb * H_ + head) * T_ + t) * DH_ + dd) = vhi; }\
    }                                                                              \
} while (0)

// One M-subtile: load A frags at row AR, do 4 n-octets x 3 passes = 12 mma.
#define GEMM_MT(N0, N1, N2, N3, AR)                 \
    ldsm4(aH, sb + G_AH + (AR) * 128 + asw);        \
    ldsm4(aL, sb + G_AL + (AR) * 128 + asw);        \
    MMA3(N0, bH0.x, bH0.y, bL0.x, bL0.y)            \
    MMA3(N1, bH0.z, bH0.w, bL0.z, bL0.w)            \
    MMA3(N2, bH1.x, bH1.y, bL1.x, bL1.y)            \
    MMA3(N3, bH1.z, bH1.w, bL1.z, bL1.w)

template <int MODE>
__global__ __launch_bounds__(256) void gemm_fused_kernel(
    const float* __restrict__ Ain,   // MODE 1: x [8192,1024]; MODE 0: ignored
    const float* __restrict__ W,     // [1024, Ntot] row-major
    const float* __restrict__ bias, float* __restrict__ out)
{
    const int Ntot = (MODE == 1) ? 3072 : 1024;
    extern __shared__ char smem[];
    const uint32_t sb = smem_u32(smem);

    const int tid  = threadIdx.x;
    const int lane = tid & 31;
    const int wid  = tid >> 5;
    const int wm   = wid & 1;       // 2 warps along M (64 rows each)
    const int wn   = wid >> 1;      // 4 warps along N (32 cols each)

    const int col0 = blockIdx.x * 128;
    const int row0 = blockIdx.y * 128;

    const float* A = (MODE == 0) ? (const float*)g_attn : Ain;

    // A copy: 128 rows, 2 threads/row, 32 fp32 each (units aU..aU+3, 128B rows)
    const int aR = tid >> 1;
    const int aC = (tid & 1) * 32;
    const int aU = (tid & 1) * 4;
    // B copy: 64 rows, 4 threads/row, 32 fp32 each (256B rows, two 128B halves)
    const int bR  = tid >> 2;
    const int bC  = (tid & 3) * 32;
    const int bHf = ((tid & 3) >> 1) * 128;   // half byte offset
    const int bU  = ((tid & 3) & 1) * 4;      // unit start within half

    F4a cA0 = {0,0,0,0}, cA1 = {0,0,0,0}, cA2 = {0,0,0,0}, cA3 = {0,0,0,0};
    F4a cB0 = {0,0,0,0}, cB1 = {0,0,0,0}, cB2 = {0,0,0,0}, cB3 = {0,0,0,0};
    F4a cC0 = {0,0,0,0}, cC1 = {0,0,0,0}, cC2 = {0,0,0,0}, cC3 = {0,0,0,0};
    F4a cD0 = {0,0,0,0}, cD1 = {0,0,0,0}, cD2 = {0,0,0,0}, cD3 = {0,0,0,0};

    const int a_r  = wm * 64 + (lane & 15);   // + mt*16 (same &7)
    const int a_s7 = a_r & 7;
    const int b_rl = lane & 15;               // + ks*16
    const int b_c0 = wn * 4 + (lane >> 4);
    const int b_c1 = b_c0 + 2;
    const int b_h0 = (b_c0 >> 3) << 7;
    const int b_u0 = b_c0 & 7;
    const int b_h1 = (b_c1 >> 3) << 7;
    const int b_u1 = b_c1 & 7;

#pragma unroll 1
    for (int kb = 0; kb < NKB; kb++) {
        const int kbase = kb * BK;

        __syncthreads();   // previous iteration's mma reads complete

        // ---- A phase: 32 fp32 -> swizzled hi/lo (128B rows) ----
        {
            const float* src = A + (size_t)(row0 + aR) * GK + kbase + aC;
#pragma unroll
            for (int j = 0; j < 2; j++) {
                float4 f0 = *(const float4*)(src + j * 16 + 0);
                float4 f1 = *(const float4*)(src + j * 16 + 4);
                float4 f2 = *(const float4*)(src + j * 16 + 8);
                float4 f3 = *(const float4*)(src + j * 16 + 12);
                uint4 hi, lo;
                cvt8(f0, f1, hi, lo);
                uint32_t off = aR * 128 + (((aU + j * 2 + 0) ^ (aR & 7)) << 4);
                *(uint4*)(smem + G_AH + off) = hi;
                *(uint4*)(smem + G_AL + off) = lo;
                cvt8(f2, f3, hi, lo);
                off = aR * 128 + (((aU + j * 2 + 1) ^ (aR & 7)) << 4);
                *(uint4*)(smem + G_AH + off) = hi;
                *(uint4*)(smem + G_AL + off) = lo;
            }
        }
        // ---- B phase: 32 fp32 -> swizzled hi/lo (256B rows, per-half) ----
        {
            const float* src = W + (size_t)(kbase + bR) * Ntot + col0 + bC;
#pragma unroll
            for (int j = 0; j < 2; j++) {
                float4 f0 = *(const float4*)(src + j * 16 + 0);
                float4 f1 = *(const float4*)(src + j * 16 + 4);
                float4 f2 = *(const float4*)(src + j * 16 + 8);
                float4 f3 = *(const float4*)(src + j * 16 + 12);
                uint4 hi, lo;
                cvt8(f0, f1, hi, lo);
                uint32_t off = bR * 256 + bHf + (((bU + j * 2 + 0) ^ (bR & 7)) << 4);
                *(uint4*)(smem + G_BH + off) = hi;
                *(uint4*)(smem + G_BL + off) = lo;
                cvt8(f2, f3, hi, lo);
                off = bR * 256 + bHf + (((bU + j * 2 + 1) ^ (bR & 7)) << 4);
                *(uint4*)(smem + G_BH + off) = hi;
                *(uint4*)(smem + G_BL + off) = lo;
            }
        }

        __syncthreads();

        // ---- mma: 4 k-steps of 16, warp tile 64x32 ----
#pragma unroll 1
        for (int ks = 0; ks < 4; ks++) {
            const int br = ks * 16 + b_rl;
            const uint32_t boff0 = br * 256 + b_h0 + ((b_u0 ^ (br & 7)) << 4);
            const uint32_t boff1 = br * 256 + b_h1 + ((b_u1 ^ (br & 7)) << 4);
            U4 bH0, bL0, bH1, bL1;
            ldsm4t(bH0, sb + G_BH + boff0);
            ldsm4t(bL0, sb + G_BL + boff0);
            ldsm4t(bH1, sb + G_BH + boff1);
            ldsm4t(bL1, sb + G_BL + boff1);

            const uint32_t asw = (uint32_t)(((2 * ks + (lane >> 4)) ^ a_s7) << 4);
            U4 aH, aL;
            GEMM_MT(cA0, cA1, cA2, cA3, a_r +  0)
            GEMM_MT(cB0, cB1, cB2, cB3, a_r + 16)
            GEMM_MT(cC0, cC1, cC2, cC3, a_r + 32)
            GEMM_MT(cD0, cD1, cD2, cD3, a_r + 48)
        }
    }

    EPI(cA0, 0, 0); EPI(cA1, 0, 1); EPI(cA2, 0, 2); EPI(cA3, 0, 3);
    EPI(cB0, 1, 0); EPI(cB1, 1, 1); EPI(cB2, 1, 2); EPI(cB3, 1, 3);
    EPI(cC0, 2, 0); EPI(cC1, 2, 1); EPI(cC2, 2, 2); EPI(cC3, 2, 3);
    EPI(cD0, 3, 0); EPI(cD1, 3, 1); EPI(cD2, 3, 2); EPI(cD3, 3, 3);
}

// ---------------------------------------------------------------------------
// RoPE on q and k in place (fp32) — verbatim.
// ---------------------------------------------------------------------------
struct RopeInv { float v[32]; };

__global__ __launch_bounds__(256) void rope_kernel(RopeInv tab) {
    const int idx = blockIdx.x * blockDim.x + threadIdx.x;
    const int d   = idx & 31;
    const int row = idx >> 5;
    const int t   = row & (T_ - 1);

    const float ang = (float)t * tab.v[d];
    float s, c;
    sincosf(ang, &s, &c);

    const size_t base = (size_t)row * DH_;
    {
        float x1 = g_q[base + d], x2 = g_q[base + d + 32];
        g_q[base + d]      = x1 * c - x2 * s;
        g_q[base + d + 32] = x1 * s + x2 * c;
    }
    {
        float x1 = g_k[base + d], x2 = g_k[base + d + 32];
        g_k[base + d]      = x1 * c - x2 * s;
        g_k[base + d + 32] = x1 * s + x2 * c;
    }
}

// ---------------------------------------------------------------------------
// Tensor-core flash attention — verbatim from passing R12 (64-query tiles,
// 83.7KB smem -> 2 CTAs/SM; the R15 experiment showed this beats wide tiles).
// ---------------------------------------------------------------------------
#define A_QH 0
#define A_QL 8192
#define A_KH 16384
#define A_KL 24576
#define A_VH 32768
#define A_VL 40960
#define A_PH 49152
#define A_PL 57344
#define A_PS 65536
#define A_MS 82944
#define A_LS 83200
#define A_CS 83456
#define ATTN_SMEM 83712

__global__ __launch_bounds__(256) void attn_mma_kernel() {
    extern __shared__ char sm8[];
    const uint32_t sb = smem_u32(sm8);
    float* Ps = (float*)(sm8 + A_PS);     // [64][68]
    float* ms = (float*)(sm8 + A_MS);
    float* ls = (float*)(sm8 + A_LS);
    float* cs = (float*)(sm8 + A_CS);

    const int tid  = threadIdx.x;
    const int lane = tid & 31;
    const int wid  = tid >> 5;
    const int wm   = wid & 1;
    const int wn   = wid >> 1;

    const int bh = blockIdx.y;
    const int qb = blockIdx.x;

    const float* Qg = g_q + (size_t)bh * (T_ * DH_) + (size_t)qb * (64 * DH_);
    const float* Kg = g_k + (size_t)bh * (T_ * DH_);
    const float* Vg = g_v + (size_t)bh * (T_ * DH_);

    const int cpR = tid >> 2;
    const int cpC = (tid & 3) * 16;
    const int cpU = (tid & 3) * 2;

    {
        const float* src = Qg + (size_t)cpR * DH_ + cpC;
        float4 f0 = *(const float4*)(src + 0);
        float4 f1 = *(const float4*)(src + 4);
        float4 f2 = *(const float4*)(src + 8);
        float4 f3 = *(const float4*)(src + 12);
        f0.x *= 0.125f; f0.y *= 0.125f; f0.z *= 0.125f; f0.w *= 0.125f;
        f1.x *= 0.125f; f1.y *= 0.125f; f1.z *= 0.125f; f1.w *= 0.125f;
        f2.x *= 0.125f; f2.y *= 0.125f; f2.z *= 0.125f; f2.w *= 0.125f;
        f3.x *= 0.125f; f3.y *= 0.125f; f3.z *= 0.125f; f3.w *= 0.125f;
        uint4 hi, lo;
        cvt8(f0, f1, hi, lo);
        uint32_t off = cpR * 128 + (((cpU + 0) ^ (cpR & 7)) << 4);
        *(uint4*)(sm8 + A_QH + off) = hi;
        *(uint4*)(sm8 + A_QL + off) = lo;
        cvt8(f2, f3, hi, lo);
        off = cpR * 128 + (((cpU + 1) ^ (cpR & 7)) << 4);
        *(uint4*)(sm8 + A_QH + off) = hi;
        *(uint4*)(sm8 + A_QL + off) = lo;
    }
    if (tid < 64) { ms[tid] = -1e30f; ls[tid] = 0.0f; }

    F4a o00 = {0,0,0,0}, o01 = {0,0,0,0};
    F4a o10 = {0,0,0,0}, o11 = {0,0,0,0};

    const int a_r  = wm * 32 + (lane & 15);
    const int a_s7 = a_r & 7;
    const int k_r  = wn * 16 + ((lane >> 4) << 3) + (lane & 7);
    const int k_c  = (lane >> 3) & 1;
    const int v_rl = lane & 15;
    const int v_ch = wn * 2 + (lane >> 4);

#pragma unroll 1
    for (int kt = 0; kt < 32; kt++) {
        __syncthreads();

        {
            const float* src = Kg + (size_t)(kt * 64 + cpR) * DH_ + cpC;
            float4 f0 = *(const float4*)(src + 0);
            float4 f1 = *(const float4*)(src + 4);
            float4 f2 = *(const float4*)(src + 8);
            float4 f3 = *(const float4*)(src + 12);
            uint4 hi, lo;
            cvt8(f0, f1, hi, lo);
            uint32_t off = cpR * 128 + (((cpU + 0) ^ (cpR & 7)) << 4);
            *(uint4*)(sm8 + A_KH + off) = hi;
            *(uint4*)(sm8 + A_KL + off) = lo;
            cvt8(f2, f3, hi, lo);
            off = cpR * 128 + (((cpU + 1) ^ (cpR & 7)) << 4);
            *(uint4*)(sm8 + A_KH + off) = hi;
            *(uint4*)(sm8 + A_KL + off) = lo;
        }
        {
            const float* src = Vg + (size_t)(kt * 64 + cpR) * DH_ + cpC;
            float4 f0 = *(const float4*)(src + 0);
            float4 f1 = *(const float4*)(src + 4);
            float4 f2 = *(const float4*)(src + 8);
            float4 f3 = *(const float4*)(src + 12);
            uint4 hi, lo;
            cvt8(f0, f1, hi, lo);
            uint32_t off = cpR * 128 + (((cpU + 0) ^ (cpR & 7)) << 4);
            *(uint4*)(sm8 + A_VH + off) = hi;
            *(uint4*)(sm8 + A_VL + off) = lo;
            cvt8(f2, f3, hi, lo);
            off = cpR * 128 + (((cpU + 1) ^ (cpR & 7)) << 4);
            *(uint4*)(sm8 + A_VH + off) = hi;
            *(uint4*)(sm8 + A_VL + off) = lo;
        }
        __syncthreads();

        {
            F4a s00 = {0,0,0,0}, s01 = {0,0,0,0};
            F4a s10 = {0,0,0,0}, s11 = {0,0,0,0};
#pragma unroll 1
            for (int ks = 0; ks < 4; ks++) {
                const uint32_t koff = k_r * 128 + (((2 * ks + k_c) ^ (k_r & 7)) << 4);
                U4 bH, bL;
                ldsm4(bH, sb + A_KH + koff);
                ldsm4(bL, sb + A_KL + koff);
                const uint32_t asw = (uint32_t)(((2 * ks + (lane >> 4)) ^ a_s7) << 4);
                U4 aH, aL;
                ldsm4(aH, sb + A_QH + a_r * 128 + asw);
                ldsm4(aL, sb + A_QL + a_r * 128 + asw);
                MMA3(s00, bH.x, bH.y, bL.x, bL.y)
                MMA3(s01, bH.z, bH.w, bL.z, bL.w)
                ldsm4(aH, sb + A_QH + (a_r + 16) * 128 + asw);
                ldsm4(aL, sb + A_QL + (a_r + 16) * 128 + asw);
                MMA3(s10, bH.x, bH.y, bL.x, bL.y)
                MMA3(s11, bH.z, bH.w, bL.z, bL.w)
            }
            const int r0 = wm * 32 + (lane >> 2);
            const int cB = wn * 16 + 2 * (lane & 3);
            *(float2*)(Ps + (r0 +  0) * 68 + cB)     = make_float2(s00.x, s00.y);
            *(float2*)(Ps + (r0 +  8) * 68 + cB)     = make_float2(s00.z, s00.w);
            *(float2*)(Ps + (r0 +  0) * 68 + cB + 8) = make_float2(s01.x, s01.y);
            *(float2*)(Ps + (r0 +  8) * 68 + cB + 8) = make_float2(s01.z, s01.w);
            *(float2*)(Ps + (r0 + 16) * 68 + cB)     = make_float2(s10.x, s10.y);
            *(float2*)(Ps + (r0 + 24) * 68 + cB)     = make_float2(s10.z, s10.w);
            *(float2*)(Ps + (r0 + 16) * 68 + cB + 8) = make_float2(s11.x, s11.y);
            *(float2*)(Ps + (r0 + 24) * 68 + cB + 8) = make_float2(s11.z, s11.w);
        }
        __syncthreads();

        {
            const int row = tid >> 2;
            const int q   = tid & 3;
            const float* pr = Ps + row * 68 + q * 16;
            float4 p0 = *(const float4*)(pr + 0);
            float4 p1 = *(const float4*)(pr + 4);
            float4 p2 = *(const float4*)(pr + 8);
            float4 p3 = *(const float4*)(pr + 12);
            float mx = fmaxf(fmaxf(fmaxf(p0.x, p0.y), fmaxf(p0.z, p0.w)),
                             fmaxf(fmaxf(p1.x, p1.y), fmaxf(p1.z, p1.w)));
            mx = fmaxf(mx, fmaxf(fmaxf(fmaxf(p2.x, p2.y), fmaxf(p2.z, p2.w)),
                                 fmaxf(fmaxf(p3.x, p3.y), fmaxf(p3.z, p3.w))));
            mx = fmaxf(mx, __shfl_xor_sync(0xffffffffu, mx, 1));
            mx = fmaxf(mx, __shfl_xor_sync(0xffffffffu, mx, 2));
            const float m_old = ms[row];
            const float m_new = fmaxf(m_old, mx);
            p0.x = __expf(p0.x - m_new); p0.y = __expf(p0.y - m_new);
            p0.z = __expf(p0.z - m_new); p0.w = __expf(p0.w - m_new);
            p1.x = __expf(p1.x - m_new); p1.y = __expf(p1.y - m_new);
            p1.z = __expf(p1.z - m_new); p1.w = __expf(p1.w - m_new);
            p2.x = __expf(p2.x - m_new); p2.y = __expf(p2.y - m_new);
            p2.z = __expf(p2.z - m_new); p2.w = __expf(p2.w - m_new);
            p3.x = __expf(p3.x - m_new); p3.y = __expf(p3.y - m_new);
            p3.z = __expf(p3.z - m_new); p3.w = __expf(p3.w - m_new);
            float sum = p0.x + p0.y + p0.z + p0.w + p1.x + p1.y + p1.z + p1.w
                      + p2.x + p2.y + p2.z + p2.w + p3.x + p3.y + p3.z + p3.w;
            sum += __shfl_xor_sync(0xffffffffu, sum, 1);
            sum += __shfl_xor_sync(0xffffffffu, sum, 2);
            const float corr = __expf(m_old - m_new);
            if (q == 0) {
                ms[row] = m_new;
                cs[row] = corr;
                ls[row] = ls[row] * corr + sum;
            }
            uint4 hi, lo;
            cvt8(p0, p1, hi, lo);
            uint32_t off = row * 128 + (((cpU + 0) ^ (row & 7)) << 4);
            *(uint4*)(sm8 + A_PH + off) = hi;
            *(uint4*)(sm8 + A_PL + off) = lo;
            cvt8(p2, p3, hi, lo);
            off = row * 128 + (((cpU + 1) ^ (row & 7)) << 4);
            *(uint4*)(sm8 + A_PH + off) = hi;
            *(uint4*)(sm8 + A_PL + off) = lo;
        }
        __syncthreads();

        {
            const int r0 = wm * 32 + (lane >> 2);
            const float c0l = cs[r0],      c0h = cs[r0 + 8];
            const float c1l = cs[r0 + 16], c1h = cs[r0 + 24];
            o00.x *= c0l; o00.y *= c0l; o00.z *= c0h; o00.w *= c0h;
            o01.x *= c0l; o01.y *= c0l; o01.z *= c0h; o01.w *= c0h;
            o10.x *= c1l; o10.y *= c1l; o10.z *= c1h; o10.w *= c1h;
            o11.x *= c1l; o11.y *= c1l; o11.z *= c1h; o11.w *= c1h;
#pragma unroll 1
            for (int ks = 0; ks < 4; ks++) {
                const int vr = ks * 16 + v_rl;
                const uint32_t voff = vr * 128 + ((v_ch ^ (vr & 7)) << 4);
                U4 bH, bL;
                ldsm4t(bH, sb + A_VH + voff);
                ldsm4t(bL, sb + A_VL + voff);
                const uint32_t asw = (uint32_t)(((2 * ks + (lane >> 4)) ^ a_s7) << 4);
                U4 aH, aL;
                ldsm4(aH, sb + A_PH + a_r * 128 + asw);
                ldsm4(aL, sb + A_PL + a_r * 128 + asw);
                MMA3(o00, bH.x, bH.y, bL.x, bL.y)
                MMA3(o01, bH.z, bH.w, bL.z, bL.w)
                ldsm4(aH, sb + A_PH + (a_r + 16) * 128 + asw);
                ldsm4(aL, sb + A_PL + (a_r + 16) * 128 + asw);
                MMA3(o10, bH.x, bH.y, bL.x, bL.y)
                MMA3(o11, bH.z, bH.w, bL.z, bL.w)
            }
        }
    }

    {
        const int r0  = wm * 32 + (lane >> 2);
        const int dcB = wn * 16 + 2 * (lane & 3);
        const float i0l = 1.0f / ls[r0],      i0h = 1.0f / ls[r0 + 8];
        const float i1l = 1.0f / ls[r0 + 16], i1h = 1.0f / ls[r0 + 24];
        const int bb = bh >> 4;
        const int h  = bh & 15;
        float* obase = g_attn + ((size_t)(bb * T_ + qb * 64)) * D_ + h * DH_;
        *(float2*)(obase + (size_t)(r0 +  0) * D_ + dcB)     = make_float2(o00.x * i0l, o00.y * i0l);
        *(float2*)(obase + (size_t)(r0 +  8) * D_ + dcB)     = make_float2(o00.z * i0h, o00.w * i0h);
        *(float2*)(obase + (size_t)(r0 +  0) * D_ + dcB + 8) = make_float2(o01.x * i0l, o01.y * i0l);
        *(float2*)(obase + (size_t)(r0 +  8) * D_ + dcB + 8) = make_float2(o01.z * i0h, o01.w * i0h);
        *(float2*)(obase + (size_t)(r0 + 16) * D_ + dcB)     = make_float2(o10.x * i1l, o10.y * i1l);
        *(float2*)(obase + (size_t)(r0 + 24) * D_ + dcB)     = make_float2(o10.z * i1h, o10.w * i1h);
        *(float2*)(obase + (size_t)(r0 + 16) * D_ + dcB + 8) = make_float2(o11.x * i1l, o11.y * i1l);
        *(float2*)(obase + (size_t)(r0 + 24) * D_ + dcB + 8) = make_float2(o11.z * i1h, o11.w * i1h);
    }
}

// ---------------------------------------------------------------------------
extern "C" void kernel_launch(void* const* d_in, const int* in_sizes, int n_in,
                              void* d_out, int out_size)
{
    const float* x     = (const float*)d_in[0];
    const float* Wqkv  = (const float*)d_in[1];
    const float* bqkv  = (const float*)d_in[2];
    const float* Wproj = (const float*)d_in[3];
    const float* bproj = (const float*)d_in[4];
    float* out = (float*)d_out;

    cudaFuncSetAttribute((const void*)gemm_fused_kernel<1>,
                         cudaFuncAttributeMaxDynamicSharedMemorySize, GEMM_SMEM);
    cudaFuncSetAttribute((const void*)gemm_fused_kernel<0>,
                         cudaFuncAttributeMaxDynamicSharedMemorySize, GEMM_SMEM);
    cudaFuncSetAttribute((const void*)attn_mma_kernel,
                         cudaFuncAttributeMaxDynamicSharedMemorySize, ATTN_SMEM);

    // 1) QKV GEMM (big 128x128 tiles) + head scatter
    gemm_fused_kernel<1><<<dim3(24, 64), 256, GEMM_SMEM>>>(x, Wqkv, bqkv, nullptr);

    // 2) RoPE
    RopeInv tab;
    for (int d = 0; d < 32; d++)
        tab.v[d] = (float)(1.0 / pow(10000.0, (double)((float)d / 32.0f)));
    rope_kernel<<<16384, 256>>>(tab);

    // 3) Flash attention (mma.sync, proven R12 64-query tiles)
    attn_mma_kernel<<<dim3(32, 64), 256, ATTN_SMEM>>>();

    // 4) Output projection (big tiles)
    gemm_fused_kernel<0><<<dim3(8, 64), 256, GEMM_SMEM>>>(nullptr, Wproj, bproj, out);
}